// round 13
// baseline (speedup 1.0000x reference)
#include <cuda_runtime.h>
#include <cuda_bf16.h>
#include <cstdint>

#define BATCH 8
#define CH    128
#define HW    3136
#define TQ    128
#define TK    64
#define QSTR  136            // padded bf16 row stride (272 B, 16B-aligned, conflict-free)
#define NT    49             // k tiles per teacher

// attn smem layout (bytes)
#define SM_Q   0
#define SM_K0  (128*QSTR*2)             // 34816
#define SM_K1  (SM_K0 + 64*QSTR*2)      // +17408
#define SM_V0  (SM_K1 + 64*QSTR*2)
#define SM_V1  (SM_V0 + 64*QSTR*2)
#define SMEM_TOTAL (SM_V1 + 64*QSTR*2)  // 104448

// proj smem layout
#define ASTR   72                        // bf16 stride for X tile rows (144 B, /16 = 9 odd)
#define PJ_A   0                         // [128 c'][64 q]   bf16 : 128*144 = 18432
#define PJ_B   (128*ASTR*2)              // [128 cout][128+pad cin] bf16 : 128*272 = 34816
#define PJ_BIAS (PJ_B + 128*QSTR*2)      // 128 floats
#define PJ_SMEM (PJ_BIAS + 512)          // 53760

// bf16 scratch: [b][pixel][c]
__device__ __nv_bfloat16 g_Q [BATCH*HW*CH];
__device__ __nv_bfloat16 g_K1[BATCH*HW*CH];
__device__ __nv_bfloat16 g_V1[BATCH*HW*CH];
__device__ __nv_bfloat16 g_K2[BATCH*HW*CH];
__device__ __nv_bfloat16 g_V2[BATCH*HW*CH];

__device__ __forceinline__ void ldsm4(uint32_t &r0, uint32_t &r1, uint32_t &r2, uint32_t &r3, uint32_t a){
    asm volatile("ldmatrix.sync.aligned.m8n8.x4.shared.b16 {%0,%1,%2,%3}, [%4];"
                 : "=r"(r0),"=r"(r1),"=r"(r2),"=r"(r3) : "r"(a));
}
__device__ __forceinline__ void ldsm4t(uint32_t &r0, uint32_t &r1, uint32_t &r2, uint32_t &r3, uint32_t a){
    asm volatile("ldmatrix.sync.aligned.m8n8.x4.trans.shared.b16 {%0,%1,%2,%3}, [%4];"
                 : "=r"(r0),"=r"(r1),"=r"(r2),"=r"(r3) : "r"(a));
}
__device__ __forceinline__ void mma16816(float* d, uint32_t a0,uint32_t a1,uint32_t a2,uint32_t a3,
                                         uint32_t b0, uint32_t b1){
    asm volatile("mma.sync.aligned.m16n8k16.row.col.f32.bf16.bf16.f32 "
                 "{%0,%1,%2,%3}, {%4,%5,%6,%7}, {%8,%9}, {%0,%1,%2,%3};"
                 : "+f"(d[0]),"+f"(d[1]),"+f"(d[2]),"+f"(d[3])
                 : "r"(a0),"r"(a1),"r"(a2),"r"(a3),"r"(b0),"r"(b1));
}
__device__ __forceinline__ void cpa16(uint32_t d, const void* s){
    asm volatile("cp.async.cg.shared.global [%0], [%1], 16;" :: "r"(d), "l"(s) : "memory");
}
#define CP_COMMIT() asm volatile("cp.async.commit_group;" ::: "memory")

// ---------------------------------------------------------------------------
// Tensor-core 1x1-conv projections. O[q][c] = sum_c' X[c'][q] * W[c][c'] + bias[c]
// A = X^T via trans-ldmatrix on [c'][q] tile; B = W via non-trans ldmatrix.
// z = 0..4 projections, z = 5: out = s copy (pre-init for attn atomics).
// ---------------------------------------------------------------------------
__global__ __launch_bounds__(256) void proj_kernel(
    const float* __restrict__ s,  const float* __restrict__ t1, const float* __restrict__ t2,
    const float* __restrict__ wq, const float* __restrict__ bq,
    const float* __restrict__ wk, const float* __restrict__ bk,
    const float* __restrict__ wv, const float* __restrict__ bv,
    float* __restrict__ out)
{
    const int b   = blockIdx.y;
    const int q0  = blockIdx.x * 64;
    const int tid = threadIdx.x;

    if (blockIdx.z == 5) {   // out = s
        const float4* sp = (const float4*)(s   + (size_t)b * CH * HW);
        float4*       op = (float4*)      (out + (size_t)b * CH * HW);
        #pragma unroll
        for (int i = 0; i < 8; i++) {
            int lin = i * 256 + tid;
            int c = lin >> 4, q4 = (lin & 15) * 4;
            op[((size_t)c * HW + q0 + q4) >> 2] = sp[((size_t)c * HW + q0 + q4) >> 2];
        }
        return;
    }

    extern __shared__ char psm[];
    __nv_bfloat16* sA = (__nv_bfloat16*)(psm + PJ_A);
    __nv_bfloat16* sB = (__nv_bfloat16*)(psm + PJ_B);
    float*      sBias = (float*)(psm + PJ_BIAS);
    const uint32_t uA = (uint32_t)__cvta_generic_to_shared(sA);
    const uint32_t uB = (uint32_t)__cvta_generic_to_shared(sB);

    const float *X, *W, *bias; __nv_bfloat16* O;
    switch (blockIdx.z) {
        case 0:  X = s;  W = wq; bias = bq; O = g_Q;  break;
        case 1:  X = t1; W = wk; bias = bk; O = g_K1; break;
        case 2:  X = t1; W = wv; bias = bv; O = g_V1; break;
        case 3:  X = t2; W = wk; bias = bk; O = g_K2; break;
        default: X = t2; W = wv; bias = bv; O = g_V2; break;
    }
    const float* Xb = X + (size_t)b * CH * HW;

    // X tile [c'=128][q=64] fp32 -> bf16 smem (same layout, coalesced)
    #pragma unroll
    for (int i = 0; i < 8; i++) {
        int cp = i * 16 + (tid >> 4);
        int q4 = (tid & 15) * 4;
        float4 x = *(const float4*)&Xb[(size_t)cp * HW + q0 + q4];
        __nv_bfloat162 l0 = __floats2bfloat162_rn(x.x, x.y);
        __nv_bfloat162 l1 = __floats2bfloat162_rn(x.z, x.w);
        uint2 u; u.x = *(uint32_t*)&l0; u.y = *(uint32_t*)&l1;
        *(uint2*)&sA[cp * ASTR + q4] = u;
    }
    // W [cout=128][cin=128] fp32 -> bf16 smem
    #pragma unroll
    for (int i = 0; i < 16; i++) {
        int co = i * 8 + (tid >> 5);
        int ci4 = (tid & 31) * 4;
        float4 w = *(const float4*)&W[co * CH + ci4];
        __nv_bfloat162 l0 = __floats2bfloat162_rn(w.x, w.y);
        __nv_bfloat162 l1 = __floats2bfloat162_rn(w.z, w.w);
        uint2 u; u.x = *(uint32_t*)&l0; u.y = *(uint32_t*)&l1;
        *(uint2*)&sB[co * QSTR + ci4] = u;
    }
    if (tid < 128) sBias[tid] = bias[tid];
    __syncthreads();

    const int warp = tid >> 5, lane = tid & 31;
    const int tA = lane >> 3, rA = lane & 7;
    const int g = lane >> 2, li = lane & 3;
    const int mb = (warp >> 1) * 16;      // 4 m-warps
    const int nb = (warp & 1) * 64;       // 2 n-warps

    // A: trans-ldmatrix on [c'][q]; matrices -> (m0,k0),(m8,k0),(m0,k8),(m8,k8)
    const uint32_t aA = uA + (uint32_t)((((tA >> 1) << 3) + rA) * ASTR + mb + ((tA & 1) << 3)) * 2;
    // B: non-trans on [cout][cin] (K-operand mirror)
    uint32_t bBo[4];
    #pragma unroll
    for (int j = 0; j < 4; j++)
        bBo[j] = uB + (uint32_t)(((nb + j * 16 + ((tA >> 1) << 3) + rA) * QSTR + ((tA & 1) << 3)) * 2);

    float Oacc[8][4];
    #pragma unroll
    for (int h = 0; h < 8; h++)
        #pragma unroll
        for (int e = 0; e < 4; e++) Oacc[h][e] = 0.f;

    #pragma unroll
    for (int ks = 0; ks < 8; ks++) {
        uint32_t a0,a1,a2,a3;
        ldsm4t(a0,a1,a2,a3, aA + (uint32_t)(ks * 16 * ASTR * 2));
        #pragma unroll
        for (int j = 0; j < 4; j++) {
            uint32_t b0,b1,b2,b3;
            ldsm4(b0,b1,b2,b3, bBo[j] + ks * 32);
            mma16816(Oacc[2*j],   a0,a1,a2,a3, b0,b1);
            mma16816(Oacc[2*j+1], a0,a1,a2,a3, b2,b3);
        }
    }

    // epilogue: + bias, bf16, store [q][c]
    __nv_bfloat16* Ob = O + ((size_t)b * HW + q0) * CH;
    const int r0 = mb + g;
    #pragma unroll
    for (int h = 0; h < 8; h++) {
        const int col = nb + h * 8 + 2 * li;
        const float bz0 = sBias[col], bz1 = sBias[col + 1];
        __nv_bfloat162 p0 = __floats2bfloat162_rn(Oacc[h][0] + bz0, Oacc[h][1] + bz1);
        __nv_bfloat162 p1 = __floats2bfloat162_rn(Oacc[h][2] + bz0, Oacc[h][3] + bz1);
        *(uint32_t*)&Ob[(size_t)r0 * CH + col]       = *(uint32_t*)&p0;
        *(uint32_t*)&Ob[(size_t)(r0 + 8) * CH + col] = *(uint32_t*)&p1;
    }
}

// ---------------------------------------------------------------------------
// FA2-style attention: one (q-tile, teacher) per CTA. 8 warps x 16 q-rows.
// S in regs -> exp -> P stays in regs -> PV in regs. cp.async double-buffered
// K/V. atomicAdd into out (pre-initialized to s).
// ---------------------------------------------------------------------------
__global__ __launch_bounds__(256, 2) void attn_kernel(float* __restrict__ out)
{
    extern __shared__ char smem[];
    const uint32_t uS = (uint32_t)__cvta_generic_to_shared(smem);
    const int tid = threadIdx.x, warp = tid >> 5, lane = tid & 31;
    const int tA = lane >> 3, rA = lane & 7;
    const int g = lane >> 2, li = lane & 3;
    const int b = blockIdx.y, t = blockIdx.z;
    const int q0 = blockIdx.x * TQ;
    const float ES = 0.08838834764831845f * 1.4426950408889634f; // C^-0.5 * log2e

    const __nv_bfloat16* Qg = g_Q + (size_t)b * HW * CH;
    const __nv_bfloat16* Kt = (t ? g_K2 : g_K1) + (size_t)b * HW * CH;
    const __nv_bfloat16* Vt = (t ? g_V2 : g_V1) + (size_t)b * HW * CH;

    const uint32_t aQ = uS + SM_Q +
        (uint32_t)(((warp * 16 + ((tA & 1) << 3) + rA) * QSTR + ((tA >> 1) << 3)) * 2);
    uint32_t bKo[4];
    #pragma unroll
    for (int j = 0; j < 4; j++)
        bKo[j] = (uint32_t)(((j * 16 + ((tA >> 1) << 3) + rA) * QSTR + ((tA & 1) << 3)) * 2);
    uint32_t bVo[8];
    #pragma unroll
    for (int h = 0; h < 8; h++)
        bVo[h] = (uint32_t)(((((tA & 1) << 3) + rA) * QSTR + h * 16 + ((tA >> 1) << 3)) * 2);

    #pragma unroll
    for (int i = 0; i < 8; i++) {
        int id = i * 256 + tid;
        int row = id >> 4, c16 = id & 15;
        int gq = q0 + row; gq = gq < HW ? gq : HW - 1;
        cpa16(uS + SM_Q + row * (QSTR * 2) + c16 * 16, Qg + (size_t)gq * CH + c16 * 8);
    }
    #pragma unroll
    for (int i = 0; i < 4; i++) {
        int id = i * 256 + tid;
        int row = id >> 4, c16 = id & 15;
        cpa16(uS + SM_K0 + row * (QSTR * 2) + c16 * 16, Kt + (size_t)row * CH + c16 * 8);
        cpa16(uS + SM_V0 + row * (QSTR * 2) + c16 * 16, Vt + (size_t)row * CH + c16 * 8);
    }
    CP_COMMIT();

    float O[16][4];
    #pragma unroll
    for (int h = 0; h < 16; h++)
        #pragma unroll
        for (int e = 0; e < 4; e++) O[h][e] = 0.f;
    float lp0 = 0.f, lp1 = 0.f;

    #pragma unroll 1
    for (int it = 0; it < NT; it++) {
        const int buf = it & 1;
        if (it + 1 < NT) {
            const int k0 = (it + 1) * TK;
            const uint32_t kb = uS + (buf ? SM_K0 : SM_K1);
            const uint32_t vb = uS + (buf ? SM_V0 : SM_V1);
            #pragma unroll
            for (int i = 0; i < 4; i++) {
                int id = i * 256 + tid;
                int row = id >> 4, c16 = id & 15;
                cpa16(kb + row * (QSTR * 2) + c16 * 16, Kt + (size_t)(k0 + row) * CH + c16 * 8);
                cpa16(vb + row * (QSTR * 2) + c16 * 16, Vt + (size_t)(k0 + row) * CH + c16 * 8);
            }
            CP_COMMIT();
            asm volatile("cp.async.wait_group 1;" ::: "memory");
        } else {
            asm volatile("cp.async.wait_group 0;" ::: "memory");
        }
        __syncthreads();

        const uint32_t kb = uS + (buf ? SM_K1 : SM_K0);
        const uint32_t vb = uS + (buf ? SM_V1 : SM_V0);

        float Sa[8][4];
        #pragma unroll
        for (int j = 0; j < 8; j++)
            #pragma unroll
            for (int e = 0; e < 4; e++) Sa[j][e] = 0.f;
        #pragma unroll
        for (int ks = 0; ks < 8; ks++) {
            uint32_t ko = ks * 32;
            uint32_t a0,a1,a2,a3;
            ldsm4(a0,a1,a2,a3, aQ + ko);
            #pragma unroll
            for (int j = 0; j < 4; j++) {
                uint32_t b0,b1,b2,b3;
                ldsm4(b0,b1,b2,b3, kb + bKo[j] + ko);
                mma16816(Sa[2*j],   a0,a1,a2,a3, b0,b1);
                mma16816(Sa[2*j+1], a0,a1,a2,a3, b2,b3);
            }
        }

        uint32_t Pa[4][4];
        #pragma unroll
        for (int h = 0; h < 4; h++) {
            #pragma unroll
            for (int c = 0; c < 2; c++) {
                float p0 = exp2f(Sa[2*h+c][0] * ES);
                float p1 = exp2f(Sa[2*h+c][1] * ES);
                float p2 = exp2f(Sa[2*h+c][2] * ES);
                float p3 = exp2f(Sa[2*h+c][3] * ES);
                lp0 += p0 + p1;
                lp1 += p2 + p3;
                __nv_bfloat162 lo = __floats2bfloat162_rn(p0, p1);
                __nv_bfloat162 hi = __floats2bfloat162_rn(p2, p3);
                Pa[h][2*c]     = *(uint32_t*)&lo;
                Pa[h][2*c + 1] = *(uint32_t*)&hi;
            }
        }

        #pragma unroll
        for (int ks = 0; ks < 4; ks++) {
            const uint32_t vkso = vb + (uint32_t)(ks * 16 * QSTR * 2);
            #pragma unroll
            for (int h = 0; h < 8; h++) {
                uint32_t v0,v1,v2,v3;
                ldsm4t(v0,v1,v2,v3, vkso + bVo[h]);
                mma16816(O[2*h],   Pa[ks][0],Pa[ks][1],Pa[ks][2],Pa[ks][3], v0,v1);
                mma16816(O[2*h+1], Pa[ks][0],Pa[ks][1],Pa[ks][2],Pa[ks][3], v2,v3);
            }
        }
        __syncthreads();
    }

    lp0 += __shfl_xor_sync(0xffffffffu, lp0, 1);
    lp0 += __shfl_xor_sync(0xffffffffu, lp0, 2);
    lp1 += __shfl_xor_sync(0xffffffffu, lp1, 1);
    lp1 += __shfl_xor_sync(0xffffffffu, lp1, 2);
    const float f0 = 0.5f / lp0;
    const float f1 = 0.5f / lp1;

    const int q  = q0 + warp * 16 + g;
    const bool v0ok = q < HW, v1ok = (q + 8) < HW;
    #pragma unroll
    for (int h = 0; h < 16; h++) {
        const int col = h * 8 + 2 * li;
        float* base = out + ((size_t)(b * CH + col)) * HW;
        if (v0ok) {
            atomicAdd(base + q,        O[h][0] * f0);
            atomicAdd(base + HW + q,   O[h][1] * f0);
        }
        if (v1ok) {
            atomicAdd(base + q + 8,      O[h][2] * f1);
            atomicAdd(base + HW + q + 8, O[h][3] * f1);
        }
    }
}

extern "C" void kernel_launch(void* const* d_in, const int* in_sizes, int n_in,
                              void* d_out, int out_size)
{
    const float* s  = (const float*)d_in[0];
    const float* t1 = (const float*)d_in[1];
    const float* t2 = (const float*)d_in[2];
    const float* wq = (const float*)d_in[3];
    const float* bq = (const float*)d_in[4];
    const float* wk = (const float*)d_in[5];
    const float* bk = (const float*)d_in[6];
    const float* wv = (const float*)d_in[7];
    const float* bv = (const float*)d_in[8];
    // inputs 9..24 (projector params) are dead code in the reference
    float* out = (float*)d_out;

    cudaFuncSetAttribute(proj_kernel, cudaFuncAttributeMaxDynamicSharedMemorySize, PJ_SMEM);
    dim3 pg(HW / 64, BATCH, 6);   // z=0..4 projections, z=5 out=s copy
    proj_kernel<<<pg, 256, PJ_SMEM>>>(s, t1, t2, wq, bq, wk, bk, wv, bv, out);

    cudaFuncSetAttribute(attn_kernel, cudaFuncAttributeMaxDynamicSharedMemorySize, SMEM_TOTAL);
    dim3 ag((HW + TQ - 1) / TQ, BATCH, 2);   // 25 x 8 x 2 teachers
    attn_kernel<<<ag, 256, SMEM_TOTAL>>>(out);
}

// round 14
// speedup vs baseline: 1.5986x; 1.5986x over previous
#include <cuda_runtime.h>
#include <cuda_bf16.h>
#include <cstdint>

#define BATCH 8
#define CH    128
#define HW    3136
#define TQ    128
#define TK    64
#define QSTR  136            // padded bf16 row stride (272 B, 16B-aligned, conflict-free)

// attn smem layout (bytes)
#define SM_Q   0
#define SM_K0  (128*QSTR*2)             // 34816
#define SM_K1  (SM_K0 + 64*QSTR*2)      // +17408
#define SM_V0  (SM_K1 + 64*QSTR*2)
#define SM_V1  (SM_V0 + 64*QSTR*2)
#define SMEM_TOTAL (SM_V1 + 64*QSTR*2)  // 104448

// proj smem layout
#define ASTR   72
#define PJ_A   0
#define PJ_B   (128*ASTR*2)
#define PJ_BIAS (PJ_B + 128*QSTR*2)
#define PJ_SMEM (PJ_BIAS + 512)         // 53760

// bf16 scratch: [b][pixel][c]
__device__ __nv_bfloat16 g_Q [BATCH*HW*CH];
__device__ __nv_bfloat16 g_K1[BATCH*HW*CH];
__device__ __nv_bfloat16 g_V1[BATCH*HW*CH];
__device__ __nv_bfloat16 g_K2[BATCH*HW*CH];
__device__ __nv_bfloat16 g_V2[BATCH*HW*CH];
// fp32 partial outputs: [part(4)][b][c][q]  (part = teacher*2 + khalf)
__device__ float g_O[4ull*BATCH*CH*HW];
// partial row sums: [part(4)][b][q]
__device__ float g_L[4*BATCH*HW];

__device__ __forceinline__ void ldsm4(uint32_t &r0, uint32_t &r1, uint32_t &r2, uint32_t &r3, uint32_t a){
    asm volatile("ldmatrix.sync.aligned.m8n8.x4.shared.b16 {%0,%1,%2,%3}, [%4];"
                 : "=r"(r0),"=r"(r1),"=r"(r2),"=r"(r3) : "r"(a));
}
__device__ __forceinline__ void ldsm4t(uint32_t &r0, uint32_t &r1, uint32_t &r2, uint32_t &r3, uint32_t a){
    asm volatile("ldmatrix.sync.aligned.m8n8.x4.trans.shared.b16 {%0,%1,%2,%3}, [%4];"
                 : "=r"(r0),"=r"(r1),"=r"(r2),"=r"(r3) : "r"(a));
}
__device__ __forceinline__ void mma16816(float* d, uint32_t a0,uint32_t a1,uint32_t a2,uint32_t a3,
                                         uint32_t b0, uint32_t b1){
    asm volatile("mma.sync.aligned.m16n8k16.row.col.f32.bf16.bf16.f32 "
                 "{%0,%1,%2,%3}, {%4,%5,%6,%7}, {%8,%9}, {%0,%1,%2,%3};"
                 : "+f"(d[0]),"+f"(d[1]),"+f"(d[2]),"+f"(d[3])
                 : "r"(a0),"r"(a1),"r"(a2),"r"(a3),"r"(b0),"r"(b1));
}
__device__ __forceinline__ void cpa16(uint32_t d, const void* s){
    asm volatile("cp.async.cg.shared.global [%0], [%1], 16;" :: "r"(d), "l"(s) : "memory");
}
#define CP_COMMIT() asm volatile("cp.async.commit_group;" ::: "memory")

// ---------------------------------------------------------------------------
// Tensor-core 1x1-conv projections. O[q][c] = sum_c' X[c'][q] * W[c][c'] + bias[c]
// ---------------------------------------------------------------------------
__global__ __launch_bounds__(256) void proj_kernel(
    const float* __restrict__ s,  const float* __restrict__ t1, const float* __restrict__ t2,
    const float* __restrict__ wq, const float* __restrict__ bq,
    const float* __restrict__ wk, const float* __restrict__ bk,
    const float* __restrict__ wv, const float* __restrict__ bv)
{
    const int b   = blockIdx.y;
    const int q0  = blockIdx.x * 64;
    const int tid = threadIdx.x;

    extern __shared__ char psm[];
    __nv_bfloat16* sA = (__nv_bfloat16*)(psm + PJ_A);
    __nv_bfloat16* sB = (__nv_bfloat16*)(psm + PJ_B);
    float*      sBias = (float*)(psm + PJ_BIAS);
    const uint32_t uA = (uint32_t)__cvta_generic_to_shared(sA);
    const uint32_t uB = (uint32_t)__cvta_generic_to_shared(sB);

    const float *X, *W, *bias; __nv_bfloat16* O;
    switch (blockIdx.z) {
        case 0:  X = s;  W = wq; bias = bq; O = g_Q;  break;
        case 1:  X = t1; W = wk; bias = bk; O = g_K1; break;
        case 2:  X = t1; W = wv; bias = bv; O = g_V1; break;
        case 3:  X = t2; W = wk; bias = bk; O = g_K2; break;
        default: X = t2; W = wv; bias = bv; O = g_V2; break;
    }
    const float* Xb = X + (size_t)b * CH * HW;

    #pragma unroll
    for (int i = 0; i < 8; i++) {
        int cp = i * 16 + (tid >> 4);
        int q4 = (tid & 15) * 4;
        float4 x = *(const float4*)&Xb[(size_t)cp * HW + q0 + q4];
        __nv_bfloat162 l0 = __floats2bfloat162_rn(x.x, x.y);
        __nv_bfloat162 l1 = __floats2bfloat162_rn(x.z, x.w);
        uint2 u; u.x = *(uint32_t*)&l0; u.y = *(uint32_t*)&l1;
        *(uint2*)&sA[cp * ASTR + q4] = u;
    }
    #pragma unroll
    for (int i = 0; i < 16; i++) {
        int co = i * 8 + (tid >> 5);
        int ci4 = (tid & 31) * 4;
        float4 w = *(const float4*)&W[co * CH + ci4];
        __nv_bfloat162 l0 = __floats2bfloat162_rn(w.x, w.y);
        __nv_bfloat162 l1 = __floats2bfloat162_rn(w.z, w.w);
        uint2 u; u.x = *(uint32_t*)&l0; u.y = *(uint32_t*)&l1;
        *(uint2*)&sB[co * QSTR + ci4] = u;
    }
    if (tid < 128) sBias[tid] = bias[tid];
    __syncthreads();

    const int warp = tid >> 5, lane = tid & 31;
    const int tA = lane >> 3, rA = lane & 7;
    const int g = lane >> 2, li = lane & 3;
    const int mb = (warp >> 1) * 16;
    const int nb = (warp & 1) * 64;

    const uint32_t aA = uA + (uint32_t)((((tA >> 1) << 3) + rA) * ASTR + mb + ((tA & 1) << 3)) * 2;
    uint32_t bBo[4];
    #pragma unroll
    for (int j = 0; j < 4; j++)
        bBo[j] = uB + (uint32_t)(((nb + j * 16 + ((tA >> 1) << 3) + rA) * QSTR + ((tA & 1) << 3)) * 2);

    float Oacc[8][4];
    #pragma unroll
    for (int h = 0; h < 8; h++)
        #pragma unroll
        for (int e = 0; e < 4; e++) Oacc[h][e] = 0.f;

    #pragma unroll
    for (int ks = 0; ks < 8; ks++) {
        uint32_t a0,a1,a2,a3;
        ldsm4t(a0,a1,a2,a3, aA + (uint32_t)(ks * 16 * ASTR * 2));
        #pragma unroll
        for (int j = 0; j < 4; j++) {
            uint32_t b0,b1,b2,b3;
            ldsm4(b0,b1,b2,b3, bBo[j] + ks * 32);
            mma16816(Oacc[2*j],   a0,a1,a2,a3, b0,b1);
            mma16816(Oacc[2*j+1], a0,a1,a2,a3, b2,b3);
        }
    }

    __nv_bfloat16* Ob = O + ((size_t)b * HW + q0) * CH;
    const int r0 = mb + g;
    #pragma unroll
    for (int h = 0; h < 8; h++) {
        const int col = nb + h * 8 + 2 * li;
        const float bz0 = sBias[col], bz1 = sBias[col + 1];
        __nv_bfloat162 p0 = __floats2bfloat162_rn(Oacc[h][0] + bz0, Oacc[h][1] + bz1);
        __nv_bfloat162 p1 = __floats2bfloat162_rn(Oacc[h][2] + bz0, Oacc[h][3] + bz1);
        *(uint32_t*)&Ob[(size_t)r0 * CH + col]       = *(uint32_t*)&p0;
        *(uint32_t*)&Ob[(size_t)(r0 + 8) * CH + col] = *(uint32_t*)&p1;
    }
}

// ---------------------------------------------------------------------------
// FA2-style attention, k-split: blockIdx.z = part = teacher*2 + khalf.
// Each part computes UNNORMALIZED partial O over its k-range + partial l,
// stores to private slices of g_O / g_L (no atomics). 800 CTAs -> ~90% waves.
// ---------------------------------------------------------------------------
__global__ __launch_bounds__(256, 2) void attn_kernel()
{
    extern __shared__ char smem[];
    const uint32_t uS = (uint32_t)__cvta_generic_to_shared(smem);
    const int tid = threadIdx.x, warp = tid >> 5, lane = tid & 31;
    const int tA = lane >> 3, rA = lane & 7;
    const int g = lane >> 2, li = lane & 3;
    const int b = blockIdx.y;
    const int p = blockIdx.z;                 // 0..3
    const int t = p >> 1, half = p & 1;
    const int ks0   = half ? 24 : 0;          // first k-tile
    const int ntile = half ? 25 : 24;
    const int q0 = blockIdx.x * TQ;
    const float ES = 0.08838834764831845f * 1.4426950408889634f; // C^-0.5 * log2e

    const __nv_bfloat16* Qg = g_Q + (size_t)b * HW * CH;
    const __nv_bfloat16* Kt = (t ? g_K2 : g_K1) + (size_t)b * HW * CH;
    const __nv_bfloat16* Vt = (t ? g_V2 : g_V1) + (size_t)b * HW * CH;

    const uint32_t aQ = uS + SM_Q +
        (uint32_t)(((warp * 16 + ((tA & 1) << 3) + rA) * QSTR + ((tA >> 1) << 3)) * 2);
    uint32_t bKo[4];
    #pragma unroll
    for (int j = 0; j < 4; j++)
        bKo[j] = (uint32_t)(((j * 16 + ((tA >> 1) << 3) + rA) * QSTR + ((tA & 1) << 3)) * 2);
    uint32_t bVo[8];
    #pragma unroll
    for (int h = 0; h < 8; h++)
        bVo[h] = (uint32_t)(((((tA & 1) << 3) + rA) * QSTR + h * 16 + ((tA >> 1) << 3)) * 2);

    // prologue: Q + first K/V tile
    #pragma unroll
    for (int i = 0; i < 8; i++) {
        int id = i * 256 + tid;
        int row = id >> 4, c16 = id & 15;
        int gq = q0 + row; gq = gq < HW ? gq : HW - 1;
        cpa16(uS + SM_Q + row * (QSTR * 2) + c16 * 16, Qg + (size_t)gq * CH + c16 * 8);
    }
    {
        const int k0 = ks0 * TK;
        #pragma unroll
        for (int i = 0; i < 4; i++) {
            int id = i * 256 + tid;
            int row = id >> 4, c16 = id & 15;
            cpa16(uS + SM_K0 + row * (QSTR * 2) + c16 * 16, Kt + (size_t)(k0 + row) * CH + c16 * 8);
            cpa16(uS + SM_V0 + row * (QSTR * 2) + c16 * 16, Vt + (size_t)(k0 + row) * CH + c16 * 8);
        }
    }
    CP_COMMIT();

    float O[16][4];
    #pragma unroll
    for (int h = 0; h < 16; h++)
        #pragma unroll
        for (int e = 0; e < 4; e++) O[h][e] = 0.f;
    float lp0 = 0.f, lp1 = 0.f;

    #pragma unroll 1
    for (int it = 0; it < ntile; it++) {
        const int buf = it & 1;
        if (it + 1 < ntile) {
            const int k0 = (ks0 + it + 1) * TK;
            const uint32_t kb = uS + (buf ? SM_K0 : SM_K1);
            const uint32_t vb = uS + (buf ? SM_V0 : SM_V1);
            #pragma unroll
            for (int i = 0; i < 4; i++) {
                int id = i * 256 + tid;
                int row = id >> 4, c16 = id & 15;
                cpa16(kb + row * (QSTR * 2) + c16 * 16, Kt + (size_t)(k0 + row) * CH + c16 * 8);
                cpa16(vb + row * (QSTR * 2) + c16 * 16, Vt + (size_t)(k0 + row) * CH + c16 * 8);
            }
            CP_COMMIT();
            asm volatile("cp.async.wait_group 1;" ::: "memory");
        } else {
            asm volatile("cp.async.wait_group 0;" ::: "memory");
        }
        __syncthreads();

        const uint32_t kb = uS + (buf ? SM_K1 : SM_K0);
        const uint32_t vb = uS + (buf ? SM_V1 : SM_V0);

        float Sa[8][4];
        #pragma unroll
        for (int j = 0; j < 8; j++)
            #pragma unroll
            for (int e = 0; e < 4; e++) Sa[j][e] = 0.f;
        #pragma unroll
        for (int ks = 0; ks < 8; ks++) {
            uint32_t ko = ks * 32;
            uint32_t a0,a1,a2,a3;
            ldsm4(a0,a1,a2,a3, aQ + ko);
            #pragma unroll
            for (int j = 0; j < 4; j++) {
                uint32_t b0,b1,b2,b3;
                ldsm4(b0,b1,b2,b3, kb + bKo[j] + ko);
                mma16816(Sa[2*j],   a0,a1,a2,a3, b0,b1);
                mma16816(Sa[2*j+1], a0,a1,a2,a3, b2,b3);
            }
        }

        uint32_t Pa[4][4];
        #pragma unroll
        for (int h = 0; h < 4; h++) {
            #pragma unroll
            for (int c = 0; c < 2; c++) {
                float p0 = exp2f(Sa[2*h+c][0] * ES);
                float p1 = exp2f(Sa[2*h+c][1] * ES);
                float p2 = exp2f(Sa[2*h+c][2] * ES);
                float p3 = exp2f(Sa[2*h+c][3] * ES);
                lp0 += p0 + p1;
                lp1 += p2 + p3;
                __nv_bfloat162 lo = __floats2bfloat162_rn(p0, p1);
                __nv_bfloat162 hi = __floats2bfloat162_rn(p2, p3);
                Pa[h][2*c]     = *(uint32_t*)&lo;
                Pa[h][2*c + 1] = *(uint32_t*)&hi;
            }
        }

        #pragma unroll
        for (int ks = 0; ks < 4; ks++) {
            const uint32_t vkso = vb + (uint32_t)(ks * 16 * QSTR * 2);
            #pragma unroll
            for (int h = 0; h < 8; h++) {
                uint32_t v0,v1,v2,v3;
                ldsm4t(v0,v1,v2,v3, vkso + bVo[h]);
                mma16816(O[2*h],   Pa[ks][0],Pa[ks][1],Pa[ks][2],Pa[ks][3], v0,v1);
                mma16816(O[2*h+1], Pa[ks][0],Pa[ks][1],Pa[ks][2],Pa[ks][3], v2,v3);
            }
        }
        __syncthreads();
    }

    // epilogue: store partial l and UNNORMALIZED partial O (plain stores)
    lp0 += __shfl_xor_sync(0xffffffffu, lp0, 1);
    lp0 += __shfl_xor_sync(0xffffffffu, lp0, 2);
    lp1 += __shfl_xor_sync(0xffffffffu, lp1, 1);
    lp1 += __shfl_xor_sync(0xffffffffu, lp1, 2);

    const int q  = q0 + warp * 16 + g;
    const bool v0ok = q < HW, v1ok = (q + 8) < HW;
    if (li == 0) {
        float* Lb = g_L + (size_t)(p * BATCH + b) * HW;
        if (v0ok) Lb[q]     = lp0;
        if (v1ok) Lb[q + 8] = lp1;
    }
    float* Op = g_O + (size_t)(p * BATCH + b) * CH * HW;
    #pragma unroll
    for (int h = 0; h < 16; h++) {
        const int col = h * 8 + 2 * li;
        float* base = Op + (size_t)col * HW;
        if (v0ok) {
            base[q]      = O[h][0];
            base[HW + q] = O[h][1];
        }
        if (v1ok) {
            base[q + 8]      = O[h][2];
            base[HW + q + 8] = O[h][3];
        }
    }
}

// ---------------------------------------------------------------------------
// combine: out = s + 0.5*(O_p0+O_p1)/l_t0 + 0.5*(O_p2+O_p3)/l_t1
// ---------------------------------------------------------------------------
__global__ __launch_bounds__(256) void combine_kernel(const float* __restrict__ s,
                                                      float* __restrict__ out)
{
    __shared__ float il[2][64];
    const int b = blockIdx.y;
    const int q0 = blockIdx.x * 64;
    const int tid = threadIdx.x;

    if (tid < 64) {
        const int q = q0 + tid;
        float l0 = g_L[(size_t)(0 * BATCH + b) * HW + q] + g_L[(size_t)(1 * BATCH + b) * HW + q];
        float l1 = g_L[(size_t)(2 * BATCH + b) * HW + q] + g_L[(size_t)(3 * BATCH + b) * HW + q];
        il[0][tid] = 0.5f / l0;
        il[1][tid] = 0.5f / l1;
    }
    __syncthreads();

    const size_t pstr = (size_t)BATCH * CH * HW;
    #pragma unroll
    for (int i = 0; i < 8; i++) {
        int lin = i * 256 + tid;
        int c = lin >> 4, q4 = (lin & 15) * 4;
        const size_t base = ((size_t)(b * CH + c)) * HW + q0 + q4;
        float4 sv = *(const float4*)&s[base];
        float4 a0 = *(const float4*)&g_O[0 * pstr + base];
        float4 a1 = *(const float4*)&g_O[1 * pstr + base];
        float4 a2 = *(const float4*)&g_O[2 * pstr + base];
        float4 a3 = *(const float4*)&g_O[3 * pstr + base];
        float4 o;
        o.x = sv.x + (a0.x + a1.x) * il[0][q4+0] + (a2.x + a3.x) * il[1][q4+0];
        o.y = sv.y + (a0.y + a1.y) * il[0][q4+1] + (a2.y + a3.y) * il[1][q4+1];
        o.z = sv.z + (a0.z + a1.z) * il[0][q4+2] + (a2.z + a3.z) * il[1][q4+2];
        o.w = sv.w + (a0.w + a1.w) * il[0][q4+3] + (a2.w + a3.w) * il[1][q4+3];
        *(float4*)&out[base] = o;
    }
}

extern "C" void kernel_launch(void* const* d_in, const int* in_sizes, int n_in,
                              void* d_out, int out_size)
{
    const float* s  = (const float*)d_in[0];
    const float* t1 = (const float*)d_in[1];
    const float* t2 = (const float*)d_in[2];
    const float* wq = (const float*)d_in[3];
    const float* bq = (const float*)d_in[4];
    const float* wk = (const float*)d_in[5];
    const float* bk = (const float*)d_in[6];
    const float* wv = (const float*)d_in[7];
    const float* bv = (const float*)d_in[8];
    // inputs 9..24 (projector params) are dead code in the reference
    float* out = (float*)d_out;

    cudaFuncSetAttribute(proj_kernel, cudaFuncAttributeMaxDynamicSharedMemorySize, PJ_SMEM);
    dim3 pg(HW / 64, BATCH, 5);
    proj_kernel<<<pg, 256, PJ_SMEM>>>(s, t1, t2, wq, bq, wk, bk, wv, bv);

    cudaFuncSetAttribute(attn_kernel, cudaFuncAttributeMaxDynamicSharedMemorySize, SMEM_TOTAL);
    dim3 ag((HW + TQ - 1) / TQ, BATCH, 4);   // 25 x 8 x (teacher,khalf)
    attn_kernel<<<ag, 256, SMEM_TOTAL>>>();

    dim3 cg(HW / 64, BATCH);
    combine_kernel<<<cg, 256>>>(s, out);
}